// round 1
// baseline (speedup 1.0000x reference)
#include <cuda_runtime.h>

// loss = mean_b( ||sum_n att_n||^2 - sum_n ||att_n||^2 ),  att_n = x_n / max(||x_n||, 1e-12)
// B=128, N=64, D=2048. One block per batch, one warp per row group.

#define B_BATCH 128
#define N_ROWS  64
#define D_COLS  2048          // 512 float4
#define NWARP   16
#define NTHREADS 512
#define EPSF    1e-12f

static __device__ double g_batch_loss[B_BATCH];

__global__ void __launch_bounds__(NTHREADS, 1)
loss_batch_kernel(const float* __restrict__ in)
{
    // smem: 16 warps x 128 float4 (one column-chunk of s partials) + reduce area
    __shared__ float4 sbuf[NWARP][128];   // 32 KB
    __shared__ double dred[2 * NWARP];    // [0..15]=diag per warp, [16..31]=ssq per warp

    const int tid  = threadIdx.x;
    const int wid  = tid >> 5;
    const int lane = tid & 31;
    const int b    = blockIdx.x;

    const float4* __restrict__ base =
        (const float4*)(in + (size_t)b * (N_ROWS * D_COLS));

    // per-lane partial of s: 16 float4 = columns (j*32 + lane)*4 .. +3
    float4 s[16];
#pragma unroll
    for (int j = 0; j < 16; ++j) s[j] = make_float4(0.f, 0.f, 0.f, 0.f);

    double diag_acc = 0.0;

    // main loop: warp wid handles rows wid, wid+16, wid+32, wid+48
    for (int r = wid; r < N_ROWS; r += NWARP) {
        const float4* __restrict__ row = base + r * (D_COLS / 4);

        // pass A: squared sum of the row (streams from DRAM/L2)
        float a0 = 0.f, a1 = 0.f, a2 = 0.f, a3 = 0.f;
#pragma unroll
        for (int j = 0; j < 16; ++j) {
            float4 v = row[j * 32 + lane];
            a0 = fmaf(v.x, v.x, a0);
            a1 = fmaf(v.y, v.y, a1);
            a2 = fmaf(v.z, v.z, a2);
            a3 = fmaf(v.w, v.w, a3);
        }
        float sq = (a0 + a1) + (a2 + a3);
#pragma unroll
        for (int o = 16; o > 0; o >>= 1)
            sq += __shfl_xor_sync(0xffffffffu, sq, o);

        float norm = sqrtf(sq);
        float nc   = fmaxf(norm, EPSF);
        float inv  = 1.0f / nc;

        if (lane == 0)
            diag_acc += (double)sq * ((double)inv * (double)inv);

        // pass B: re-read row (L1 hit) and accumulate s += x * inv
#pragma unroll
        for (int j = 0; j < 16; ++j) {
            float4 v = row[j * 32 + lane];
            s[j].x = fmaf(v.x, inv, s[j].x);
            s[j].y = fmaf(v.y, inv, s[j].y);
            s[j].z = fmaf(v.z, inv, s[j].z);
            s[j].w = fmaf(v.w, inv, s[j].w);
        }
    }

    if (lane == 0) dred[wid] = diag_acc;

    // cross-warp reduction of s, in 4 column-chunks of 128 float4 each.
    // ssq accumulated in double by threads 0..127.
    double ssq = 0.0;
#pragma unroll
    for (int c = 0; c < 4; ++c) {
        __syncthreads();
        // each warp publishes its partial for columns chunk c
#pragma unroll
        for (int jj = 0; jj < 4; ++jj)
            sbuf[wid][jj * 32 + lane] = s[c * 4 + jj];
        __syncthreads();
        if (tid < 128) {
            float4 tot = sbuf[0][tid];
#pragma unroll
            for (int w = 1; w < NWARP; ++w) {
                float4 p = sbuf[w][tid];
                tot.x += p.x; tot.y += p.y; tot.z += p.z; tot.w += p.w;
            }
            ssq += (double)tot.x * (double)tot.x;
            ssq += (double)tot.y * (double)tot.y;
            ssq += (double)tot.z * (double)tot.z;
            ssq += (double)tot.w * (double)tot.w;
        }
    }

    // reduce ssq across the block
#pragma unroll
    for (int o = 16; o > 0; o >>= 1)
        ssq += __shfl_xor_sync(0xffffffffu, ssq, o);
    if (lane == 0) dred[NWARP + wid] = ssq;
    __syncthreads();

    if (tid == 0) {
        double S = 0.0, Dg = 0.0;
#pragma unroll
        for (int w = 0; w < NWARP; ++w) { Dg += dred[w]; S += dred[NWARP + w]; }
        g_batch_loss[b] = S - Dg;
    }
}

__global__ void loss_final_kernel(float* __restrict__ out)
{
    __shared__ double acc[4];
    const int t = threadIdx.x;           // 128 threads
    double v = g_batch_loss[t];
#pragma unroll
    for (int o = 16; o > 0; o >>= 1)
        v += __shfl_xor_sync(0xffffffffu, v, o);
    if ((t & 31) == 0) acc[t >> 5] = v;
    __syncthreads();
    if (t == 0)
        out[0] = (float)(((acc[0] + acc[1]) + (acc[2] + acc[3])) / (double)B_BATCH);
}

extern "C" void kernel_launch(void* const* d_in, const int* in_sizes, int n_in,
                              void* d_out, int out_size)
{
    (void)in_sizes; (void)n_in; (void)out_size;
    const float* in = (const float*)d_in[0];
    float* out = (float*)d_out;

    loss_batch_kernel<<<B_BATCH, NTHREADS>>>(in);
    loss_final_kernel<<<1, 128>>>(out);
}